// round 16
// baseline (speedup 1.0000x reference)
#include <cuda_runtime.h>
#include <cuda_fp16.h>
#include <cstdint>

// ---------------------------------------------------------------------------
// Problem dims
// ---------------------------------------------------------------------------
static constexpr int T_ = 8192;   // tokens (M)
static constexpr int O_ = 4096;   // out features (N)
static constexpr int I_ = 4096;   // in features (K)
static constexpr int G_ = I_ / 256;

// ---------------------------------------------------------------------------
// Scratch (device globals — no runtime allocation allowed)
// ---------------------------------------------------------------------------
__device__ __half g_xq[(size_t)T_ * I_];   // (q - zp), exact integer in fp16
__device__ __half g_wq[(size_t)O_ * I_];   // (w - z) * s in fp16
__device__ float  g_sx[T_];                // per-token activation scale
__device__ int    g_tile_ctr;              // dynamic tile counter
__device__ int    g_bcnt[32];              // weight B-block readiness counters

// ---------------------------------------------------------------------------
// PTX helpers (classic path; tcgen05 not available: toolchain targets sm_103)
// ---------------------------------------------------------------------------
__device__ __forceinline__ void cp_async16(uint32_t saddr, const void* gptr) {
    asm volatile("cp.async.cg.shared.global [%0], [%1], 16;\n"
                 :: "r"(saddr), "l"(gptr) : "memory");
}
__device__ __forceinline__ void cp_commit() {
    asm volatile("cp.async.commit_group;\n" ::: "memory");
}
template <int N>
__device__ __forceinline__ void cp_wait() {
    asm volatile("cp.async.wait_group %0;\n" :: "n"(N) : "memory");
}
__device__ __forceinline__ uint32_t smem_u32(const void* p) {
    uint32_t a;
    asm("{ .reg .u64 t; cvta.to.shared.u64 t, %1; cvt.u32.u64 %0, t; }"
        : "=r"(a) : "l"(p));
    return a;
}
__device__ __forceinline__ void ldmatrix_x4(uint32_t (&r)[4], uint32_t addr) {
    asm volatile("ldmatrix.sync.aligned.m8n8.x4.shared.b16 {%0,%1,%2,%3}, [%4];\n"
                 : "=r"(r[0]), "=r"(r[1]), "=r"(r[2]), "=r"(r[3]) : "r"(addr));
}
__device__ __forceinline__ void mma16816(float (&d)[4], const uint32_t (&a)[4],
                                         uint32_t b0, uint32_t b1) {
    asm volatile(
        "mma.sync.aligned.m16n8k16.row.col.f32.f16.f16.f32 "
        "{%0,%1,%2,%3}, {%4,%5,%6,%7}, {%8,%9}, {%0,%1,%2,%3};\n"
        : "+f"(d[0]), "+f"(d[1]), "+f"(d[2]), "+f"(d[3])
        : "r"(a[0]), "r"(a[1]), "r"(a[2]), "r"(a[3]), "r"(b0), "r"(b1));
}

// ---------------------------------------------------------------------------
// Prep kernel: ACTIVATIONS ONLY (one 256-thread block per token row).
// Also resets the tile counter and the weight-block readiness counters for
// the gemm launch that follows in stream order (race-free by construction).
// ---------------------------------------------------------------------------
__global__ void __launch_bounds__(256) prep_kernel(const float* __restrict__ x,
                                                   int gemm_grid) {
    const int tid = threadIdx.x;
    if (blockIdx.x == 0) {
        if (tid < 32) g_bcnt[tid] = 0;
        if (tid == 32) g_tile_ctr = gemm_grid;
    }
    const int row = blockIdx.x;
    const float4* xr = reinterpret_cast<const float4*>(x) + (size_t)row * (I_ / 4);

    float4 v[4];
    float mn = 0.0f, mx = 0.0f;
#pragma unroll
    for (int j = 0; j < 4; ++j) {
        v[j] = xr[tid + 256 * j];
        mn = fminf(mn, fminf(fminf(v[j].x, v[j].y), fminf(v[j].z, v[j].w)));
        mx = fmaxf(mx, fmaxf(fmaxf(v[j].x, v[j].y), fmaxf(v[j].z, v[j].w)));
    }
#pragma unroll
    for (int o = 16; o > 0; o >>= 1) {
        mn = fminf(mn, __shfl_xor_sync(0xffffffffu, mn, o));
        mx = fmaxf(mx, __shfl_xor_sync(0xffffffffu, mx, o));
    }
    __shared__ float smn[8], smx[8];
    if ((tid & 31) == 0) { smn[tid >> 5] = mn; smx[tid >> 5] = mx; }
    __syncthreads();
    mn = smn[0]; mx = smx[0];
#pragma unroll
    for (int wi = 1; wi < 8; ++wi) { mn = fminf(mn, smn[wi]); mx = fmaxf(mx, smx[wi]); }

    const float scale = fmaxf(__fdiv_rn(mx - mn, 255.0f), 1.1920929e-07f);
    const float dmin = __fdiv_rn(mn, scale);
    const float dmax = __fdiv_rn(mx, scale);
    float zp = ((-128.0f + dmin) + (127.0f + dmax) > 0.0f)
                   ? (-128.0f - dmin) : (127.0f - dmax);
    zp = rintf(fminf(fmaxf(zp, -128.0f), 127.0f));

    const float rs = __fdiv_rn(1.0f, scale);
    const float lo = -128.0f - zp;
    const float hi = 127.0f - zp;

    __half* out = g_xq + (size_t)row * I_;
#pragma unroll
    for (int j = 0; j < 4; ++j) {
        float f[4] = {v[j].x, v[j].y, v[j].z, v[j].w};
        __align__(8) __half h[4];
#pragma unroll
        for (int e = 0; e < 4; ++e)
            h[e] = __float2half_rn(fminf(fmaxf(rintf(f[e] * rs), lo), hi));
        *reinterpret_cast<uint2*>(out + (size_t)(tid + 256 * j) * 4) =
            *reinterpret_cast<const uint2*>(h);
    }
    if (tid == 0) g_sx[row] = scale;
}

// ---------------------------------------------------------------------------
// Persistent GEMM with in-kernel weight dequant overlap.
// Last PREP_CTAS CTAs dequantize the 4096 weight rows first (warp-per-row,
// interleaved so B blocks complete in ascending pair order), then join GEMM.
// GEMM CTAs gate only the first prefetch of each tile's B block on
// g_bcnt[n] >= 128 (tid0 spin + __syncthreads; uniform branch; producers are
// independent CTAs -> deadlock-free; all CTAs co-resident at 2/SM).
// Main loop/epilogue byte-identical to the proven R14/R15 kernel.
// ---------------------------------------------------------------------------
static constexpr int BM = 128;
static constexpr int BN = 128;
static constexpr int BK = 64;
static constexpr int NUM_KT = I_ / BK;         // 64 stages per tile
static constexpr int NTILES = (T_ / BM) * (O_ / BN);   // 2048
static constexpr int A_ST = BM * 128;          // 16 KB
static constexpr int ST = 2 * A_ST;            // 32 KB per stage
static constexpr int GEMM_SMEM = 3 * ST + 256; // ~96.25 KB -> 2 CTAs/SM
static constexpr int PREP_CTAS = 64;           // 256 weight-prep warps

__device__ __forceinline__ uint32_t swz(uint32_t row, uint32_t ch) {
    return row * 128u + ((ch ^ (row & 7u)) << 4);
}

__global__ void __launch_bounds__(128, 2) gemm_kernel(float* __restrict__ C,
                                                      const int* __restrict__ w,
                                                      const float* __restrict__ scales,
                                                      const float* __restrict__ zeros) {
    extern __shared__ char dsm[];
    __shared__ int s_nt;
    const uint32_t sbase = (smem_u32(dsm) + 127u) & ~127u;

    const int tid = threadIdx.x;
    const int lane = tid & 31;
    const int wid = tid >> 5;
    const int wm = wid >> 1;
    const int wn = wid & 1;
    const int prep_start = (int)gridDim.x - PREP_CTAS;

    // ---- role: weight dequant (last PREP_CTAS CTAs), warp-per-row ---------
    if ((int)blockIdx.x >= prep_start) {
        const int wg = ((int)blockIdx.x - prep_start) * 4 + wid;   // 0..255
#pragma unroll 1
        for (int i = 0; i < 16; ++i) {
            const int row = i * 256 + wg;           // blocks done in pair order
            const int4* wp = reinterpret_cast<const int4*>(w + (size_t)row * I_);
            __half* dst = g_wq + (size_t)row * I_;
            const float* srow = scales + row * G_;
            const float* zrow = zeros + row * G_;
#pragma unroll 4
            for (int c = 0; c < 32; ++c) {
                const int idx4 = c * 32 + lane;     // int4 index in row
                const int col = idx4 * 4;
                const int g = col >> 8;             // all 4 elems same group
                const float s = srow[g];
                const float zs = zrow[g] * s;
                const int4 a = wp[idx4];
                __align__(8) __half h[4];
                h[0] = __float2half_rn(__fmaf_rn((float)a.x, s, -zs));
                h[1] = __float2half_rn(__fmaf_rn((float)a.y, s, -zs));
                h[2] = __float2half_rn(__fmaf_rn((float)a.z, s, -zs));
                h[3] = __float2half_rn(__fmaf_rn((float)a.w, s, -zs));
                *reinterpret_cast<uint2*>(dst + col) =
                    *reinterpret_cast<const uint2*>(h);
            }
            __syncwarp();
            if (lane == 0) {
                __threadfence();                    // wq rows visible (L2)
                atomicAdd(&g_bcnt[row >> 7], 1);    // 128 per block
            }
        }
    }

    // ---- hoisted producer addressing ---------------------------------------
    uint32_t goff[8], soff[8];
#pragma unroll
    for (int i = 0; i < 8; ++i) {
        const int c = tid + i * 128;
        const int row = c >> 3, ch = c & 7;
        goff[i] = (uint32_t)(row * I_ + ch * 8);
        soff[i] = swz(row, ch);
    }

    const uint32_t arow[4] = {
        (uint32_t)(wm * 64 +  0 + (lane & 15)), (uint32_t)(wm * 64 + 16 + (lane & 15)),
        (uint32_t)(wm * 64 + 32 + (lane & 15)), (uint32_t)(wm * 64 + 48 + (lane & 15))};
    const uint32_t brow[4] = {
        (uint32_t)(wn * 64 +  0 + (lane & 7) + (((lane >> 4) & 1) << 3)),
        (uint32_t)(wn * 64 + 16 + (lane & 7) + (((lane >> 4) & 1) << 3)),
        (uint32_t)(wn * 64 + 32 + (lane & 7) + (((lane >> 4) & 1) << 3)),
        (uint32_t)(wn * 64 + 48 + (lane & 7) + (((lane >> 4) & 1) << 3))};
    const uint32_t acbit = (lane >> 4) & 1;
    const uint32_t bcbit = (lane >> 3) & 1;

    float acc[4][8][4];
#pragma unroll
    for (int a = 0; a < 4; ++a)
#pragma unroll
        for (int b = 0; b < 8; ++b)
#pragma unroll
            for (int c = 0; c < 4; ++c) acc[a][b][c] = 0.0f;

    auto issue_tile = [&](const __half* A, const __half* B, int s, int b) {
        const uint32_t sa = sbase + (uint32_t)b * ST;
        const __half* As = A + s * BK;
        const __half* Bs = B + s * BK;
#pragma unroll
        for (int i = 0; i < 8; ++i) {
            cp_async16(sa + soff[i],        As + goff[i]);
            cp_async16(sa + A_ST + soff[i], Bs + goff[i]);
        }
        cp_commit();
    };

    int tile = blockIdx.x;                     // first tile: static
    {
        // Gate on this tile's B block being dequantized (A ready by stream
        // order). tid0 spin + barrier: uniform, producers independent.
        if (tid == 0) {
            const volatile int* p = (const volatile int*)&g_bcnt[tile & 31];
            while (*p < 128) { }
        }
        __syncthreads();
        const __half* A0 = g_xq + (size_t)((tile >> 5) * BM) * I_;
        const __half* B0 = g_wq + (size_t)((tile & 31) * BN) * I_;
        issue_tile(A0, B0, 0, 0);
        issue_tile(A0, B0, 1, 1);
    }
    int buf = 0;

    uint32_t afr[4][4], bfr[4][4];

    while (tile < NTILES) {
        const int m0 = (tile >> 5) * BM;
        const int n0 = (tile & 31) * BN;
        const __half* Ag = g_xq + (size_t)m0 * I_;
        const __half* Bg = g_wq + (size_t)n0 * I_;

        if (tid == 0) s_nt = atomicAdd(&g_tile_ctr, 1);   // claim next tile

        int nt = NTILES;
        const __half* An = Ag;
        const __half* Bn = Bg;

        for (int s = 0; s < NUM_KT; ++s) {
            cp_wait<1>();
            __syncthreads();                     // RAW stage-s; WAR prefetch buf;
                                                 // publishes s_nt at s==0
            if (s == 0) {
                nt = s_nt;
                if (nt < NTILES) {
                    An = g_xq + (size_t)((nt >> 5) * BM) * I_;
                    Bn = g_wq + (size_t)((nt & 31) * BN) * I_;
                }
            }

            const uint32_t bA = sbase + (uint32_t)buf * ST;
            const uint32_t bB = bA + A_ST;

#pragma unroll
            for (int mi = 0; mi < 4; ++mi)
                ldmatrix_x4(afr[mi],
                            bA + arow[mi] * 128 + ((acbit ^ (arow[mi] & 7)) << 4));
#pragma unroll
            for (int np = 0; np < 4; ++np)
                ldmatrix_x4(bfr[np],
                            bB + brow[np] * 128 + ((bcbit ^ (brow[np] & 7)) << 4));

            const int pbuf = buf ? buf - 1 : 2;  // (buf+2)%3
            const int ps = s + 2;
            if (ps < NUM_KT) {
                issue_tile(Ag, Bg, ps, pbuf);
            } else if (nt < NTILES) {
                // Gate the next tile's B block (uniform branch: nt/ps uniform).
                if (tid == 0) {
                    const volatile int* p = (const volatile int*)&g_bcnt[nt & 31];
                    while (*p < 128) { }
                }
                __syncthreads();
                issue_tile(An, Bn, ps - NUM_KT, pbuf);
            } else {
                cp_commit();                     // uniform group accounting
            }

#pragma unroll
            for (int ks = 0; ks < 4; ++ks) {
                const uint32_t ach = (uint32_t)((ks + 1) * 2) + acbit;
                const uint32_t bch = (uint32_t)((ks + 1) * 2) + bcbit;
#pragma unroll
                for (int mi = 0; mi < 4; ++mi) {
#pragma unroll
                    for (int ni = 0; ni < 8; ++ni)
                        mma16816(acc[mi][ni], afr[mi],
                                 bfr[ni >> 1][(ni & 1) * 2],
                                 bfr[ni >> 1][(ni & 1) * 2 + 1]);
                    if (ks < 3)
                        ldmatrix_x4(afr[mi],
                                    bA + arow[mi] * 128 + ((ach ^ (arow[mi] & 7)) << 4));
                }
                if (ks < 3) {
#pragma unroll
                    for (int np = 0; np < 4; ++np)
                        ldmatrix_x4(bfr[np],
                                    bB + brow[np] * 128 + ((bch ^ (brow[np] & 7)) << 4));
                }
            }
            buf = (buf == 2) ? 0 : buf + 1;
        }

        // Epilogue (overlaps the next tile's in-flight loads)
#pragma unroll
        for (int mi = 0; mi < 4; ++mi) {
            const int grow = m0 + wm * 64 + mi * 16 + (lane >> 2);
            const float s0 = g_sx[grow];
            const float s1 = g_sx[grow + 8];
#pragma unroll
            for (int ni = 0; ni < 8; ++ni) {
                const int gcol = n0 + wn * 64 + ni * 8 + (lane & 3) * 2;
                float2 v0, v1;
                v0.x = acc[mi][ni][0] * s0; v0.y = acc[mi][ni][1] * s0;
                v1.x = acc[mi][ni][2] * s1; v1.y = acc[mi][ni][3] * s1;
                *reinterpret_cast<float2*>(C + (size_t)grow * O_ + gcol) = v0;
                *reinterpret_cast<float2*>(C + (size_t)(grow + 8) * O_ + gcol) = v1;
            }
        }

        tile = nt;
        if (tile < NTILES) {
#pragma unroll
            for (int a = 0; a < 4; ++a)
#pragma unroll
                for (int b = 0; b < 8; ++b)
#pragma unroll
                    for (int c = 0; c < 4; ++c) acc[a][b][c] = 0.0f;
        }
    }
}

// ---------------------------------------------------------------------------
// Launch
// ---------------------------------------------------------------------------
extern "C" void kernel_launch(void* const* d_in, const int* in_sizes, int n_in,
                              void* d_out, int out_size) {
    const float* x = (const float*)d_in[0];
    const int* w = (const int*)d_in[1];
    const float* scales = (const float*)d_in[2];
    const float* zeros = (const float*)d_in[3];
    float* out = (float*)d_out;

    static int nCTA = 0;
    if (nCTA == 0) {
        cudaFuncSetAttribute(gemm_kernel,
                             cudaFuncAttributeMaxDynamicSharedMemorySize,
                             GEMM_SMEM);
        int sms = 0;
        cudaDeviceGetAttribute(&sms, cudaDevAttrMultiProcessorCount, 0);
        nCTA = 2 * (sms > 0 ? sms : 148);
        if (nCTA > NTILES) nCTA = NTILES;
    }

    prep_kernel<<<T_, 256>>>(x, nCTA);
    gemm_kernel<<<nCTA, 128, GEMM_SMEM>>>(out, w, scales, zeros);
}

// round 17
// speedup vs baseline: 1.6434x; 1.6434x over previous
#include <cuda_runtime.h>
#include <cuda_fp16.h>
#include <cstdint>

// ---------------------------------------------------------------------------
// Problem dims
// ---------------------------------------------------------------------------
static constexpr int T_ = 8192;   // tokens (M)
static constexpr int O_ = 4096;   // out features (N)
static constexpr int I_ = 4096;   // in features (K)
static constexpr int G_ = I_ / 256;

// ---------------------------------------------------------------------------
// Scratch (device globals — no runtime allocation allowed)
// ---------------------------------------------------------------------------
__device__ __half g_xq[(size_t)T_ * I_];   // (q - zp), exact integer in fp16
__device__ __half g_wq[(size_t)O_ * I_];   // (w - z) * s in fp16
__device__ float  g_sx[T_];                // per-token activation scale
__device__ int    g_tile_ctr;              // dynamic tile counter

// ---------------------------------------------------------------------------
// PTX helpers (classic path; tcgen05 not available: toolchain targets sm_103)
// ---------------------------------------------------------------------------
__device__ __forceinline__ void cp_async16(uint32_t saddr, const void* gptr) {
    asm volatile("cp.async.cg.shared.global [%0], [%1], 16;\n"
                 :: "r"(saddr), "l"(gptr) : "memory");
}
__device__ __forceinline__ void cp_commit() {
    asm volatile("cp.async.commit_group;\n" ::: "memory");
}
template <int N>
__device__ __forceinline__ void cp_wait() {
    asm volatile("cp.async.wait_group %0;\n" :: "n"(N) : "memory");
}
__device__ __forceinline__ uint32_t smem_u32(const void* p) {
    uint32_t a;
    asm("{ .reg .u64 t; cvta.to.shared.u64 t, %1; cvt.u32.u64 %0, t; }"
        : "=r"(a) : "l"(p));
    return a;
}
__device__ __forceinline__ void ldmatrix_x4(uint32_t (&r)[4], uint32_t addr) {
    asm volatile("ldmatrix.sync.aligned.m8n8.x4.shared.b16 {%0,%1,%2,%3}, [%4];\n"
                 : "=r"(r[0]), "=r"(r[1]), "=r"(r[2]), "=r"(r[3]) : "r"(addr));
}
__device__ __forceinline__ void mma16816(float (&d)[4], const uint32_t (&a)[4],
                                         uint32_t b0, uint32_t b1) {
    asm volatile(
        "mma.sync.aligned.m16n8k16.row.col.f32.f16.f16.f32 "
        "{%0,%1,%2,%3}, {%4,%5,%6,%7}, {%8,%9}, {%0,%1,%2,%3};\n"
        : "+f"(d[0]), "+f"(d[1]), "+f"(d[2]), "+f"(d[3])
        : "r"(a[0]), "r"(a[1]), "r"(a[2]), "r"(a[3]), "r"(b0), "r"(b1));
}

// ---------------------------------------------------------------------------
// Fused prep kernel. Activation branch uses a per-row reciprocal and folded
// zero-point clamp: clamp(rint(x*rs)+zp,-128,127)-zp == clamp(rint(x*rs),
// -128-zp, 127-zp) exactly (zp integral). Weight branch folds (w-z)*s into
// FFMA with zs = z*s. Both verified at rel_err 2.121765e-4.
// ---------------------------------------------------------------------------
__global__ void __launch_bounds__(256) prep_kernel(const float* __restrict__ x,
                                                   const int* __restrict__ w,
                                                   const float* __restrict__ scales,
                                                   const float* __restrict__ zeros,
                                                   int gemm_grid) {
    const int tid = threadIdx.x;
    if (blockIdx.x == 0 && tid == 0) g_tile_ctr = gemm_grid;
    if (blockIdx.x < T_) {
        const int row = blockIdx.x;
        const float4* xr =
            reinterpret_cast<const float4*>(x) + (size_t)row * (I_ / 4);

        float4 v[4];
        float mn = 0.0f, mx = 0.0f;
#pragma unroll
        for (int j = 0; j < 4; ++j) {
            v[j] = xr[tid + 256 * j];
            mn = fminf(mn, fminf(fminf(v[j].x, v[j].y), fminf(v[j].z, v[j].w)));
            mx = fmaxf(mx, fmaxf(fmaxf(v[j].x, v[j].y), fmaxf(v[j].z, v[j].w)));
        }
#pragma unroll
        for (int o = 16; o > 0; o >>= 1) {
            mn = fminf(mn, __shfl_xor_sync(0xffffffffu, mn, o));
            mx = fmaxf(mx, __shfl_xor_sync(0xffffffffu, mx, o));
        }
        __shared__ float smn[8], smx[8];
        if ((tid & 31) == 0) { smn[tid >> 5] = mn; smx[tid >> 5] = mx; }
        __syncthreads();
        mn = smn[0]; mx = smx[0];
#pragma unroll
        for (int wi = 1; wi < 8; ++wi) {
            mn = fminf(mn, smn[wi]); mx = fmaxf(mx, smx[wi]);
        }

        const float scale = fmaxf(__fdiv_rn(mx - mn, 255.0f), 1.1920929e-07f);
        const float dmin = __fdiv_rn(mn, scale);
        const float dmax = __fdiv_rn(mx, scale);
        float zp = ((-128.0f + dmin) + (127.0f + dmax) > 0.0f)
                       ? (-128.0f - dmin) : (127.0f - dmax);
        zp = rintf(fminf(fmaxf(zp, -128.0f), 127.0f));

        const float rs = __fdiv_rn(1.0f, scale);   // one IEEE div per row
        const float lo = -128.0f - zp;             // exact (zp integral)
        const float hi = 127.0f - zp;

        __half* out = g_xq + (size_t)row * I_;
#pragma unroll
        for (int j = 0; j < 4; ++j) {
            float f[4] = {v[j].x, v[j].y, v[j].z, v[j].w};
            __align__(8) __half h[4];
#pragma unroll
            for (int e = 0; e < 4; ++e) {
                h[e] = __float2half_rn(
                    fminf(fmaxf(rintf(f[e] * rs), lo), hi));
            }
            *reinterpret_cast<uint2*>(out + (size_t)(tid + 256 * j) * 4) =
                *reinterpret_cast<const uint2*>(h);
        }
        if (tid == 0) g_sx[row] = scale;
    } else {
        const int t = (blockIdx.x - T_) * 256 + tid;
        const int row = t >> 9;
        const int col = (t & 511) << 3;
        const int g = col >> 8;
        const float s = scales[row * G_ + g];
        const float zs = zeros[row * G_ + g] * s;  // fold: (w-z)*s = w*s - z*s
        const int4* wp = reinterpret_cast<const int4*>(w + (size_t)row * I_ + col);
        const int4 a = wp[0], b = wp[1];
        __align__(16) __half h[8];
        h[0] = __float2half_rn(__fmaf_rn((float)a.x, s, -zs));
        h[1] = __float2half_rn(__fmaf_rn((float)a.y, s, -zs));
        h[2] = __float2half_rn(__fmaf_rn((float)a.z, s, -zs));
        h[3] = __float2half_rn(__fmaf_rn((float)a.w, s, -zs));
        h[4] = __float2half_rn(__fmaf_rn((float)b.x, s, -zs));
        h[5] = __float2half_rn(__fmaf_rn((float)b.y, s, -zs));
        h[6] = __float2half_rn(__fmaf_rn((float)b.z, s, -zs));
        h[7] = __float2half_rn(__fmaf_rn((float)b.w, s, -zs));
        *reinterpret_cast<uint4*>(g_wq + (size_t)row * I_ + col) =
            *reinterpret_cast<const uint4*>(h);
    }
}

// ---------------------------------------------------------------------------
// Persistent GEMM with dynamic tile stealing (best measured configuration:
// 556.0us @ 81.4% tensor). 128x128 tile, BK=64, 3-stage cp.async pipeline,
// 128 threads (4 warps, 2x2 of 64x64 warp tiles), 2 CTAs/SM. Continuous
// stage stream across tiles; next tile claimed via atomicAdd at tile start
// (ATOMG latency hidden under ~5000 cycles of tensor work). cp.async issued
// only AFTER the WAR __syncthreads (R10 rule); one cp_commit per stage per
// warp always.
// ---------------------------------------------------------------------------
static constexpr int BM = 128;
static constexpr int BN = 128;
static constexpr int BK = 64;                  // halves per stage = 128B rows
static constexpr int NUM_KT = I_ / BK;         // 64 stages per tile
static constexpr int NTILES = (T_ / BM) * (O_ / BN);   // 2048
static constexpr int A_ST = BM * 128;          // 16 KB
static constexpr int ST = 2 * A_ST;            // 32 KB per stage (A+B)
static constexpr int GEMM_SMEM = 3 * ST + 256; // ~96.25 KB -> 2 CTAs/SM

__device__ __forceinline__ uint32_t swz(uint32_t row, uint32_t ch) {
    return row * 128u + ((ch ^ (row & 7u)) << 4);
}

__global__ void __launch_bounds__(128, 2) gemm_kernel(float* __restrict__ C) {
    extern __shared__ char dsm[];
    __shared__ int s_nt;                       // next-tile broadcast slot
    const uint32_t sbase = (smem_u32(dsm) + 127u) & ~127u;

    const int tid = threadIdx.x;
    const int lane = tid & 31;
    const int wid = tid >> 5;
    const int wm = wid >> 1;      // 0..1 : 64-row band
    const int wn = wid & 1;       // 0..1 : 64-col band

    uint32_t goff[8], soff[8];
#pragma unroll
    for (int i = 0; i < 8; ++i) {
        const int c = tid + i * 128;          // 0..1023
        const int row = c >> 3, ch = c & 7;
        goff[i] = (uint32_t)(row * I_ + ch * 8);
        soff[i] = swz(row, ch);
    }

    const uint32_t arow[4] = {
        (uint32_t)(wm * 64 +  0 + (lane & 15)), (uint32_t)(wm * 64 + 16 + (lane & 15)),
        (uint32_t)(wm * 64 + 32 + (lane & 15)), (uint32_t)(wm * 64 + 48 + (lane & 15))};
    const uint32_t brow[4] = {
        (uint32_t)(wn * 64 +  0 + (lane & 7) + (((lane >> 4) & 1) << 3)),
        (uint32_t)(wn * 64 + 16 + (lane & 7) + (((lane >> 4) & 1) << 3)),
        (uint32_t)(wn * 64 + 32 + (lane & 7) + (((lane >> 4) & 1) << 3)),
        (uint32_t)(wn * 64 + 48 + (lane & 7) + (((lane >> 4) & 1) << 3))};
    const uint32_t acbit = (lane >> 4) & 1;   // A chunk low bit
    const uint32_t bcbit = (lane >> 3) & 1;   // B chunk low bit

    float acc[4][8][4];
#pragma unroll
    for (int a = 0; a < 4; ++a)
#pragma unroll
        for (int b = 0; b < 8; ++b)
#pragma unroll
            for (int c = 0; c < 4; ++c) acc[a][b][c] = 0.0f;

    auto issue_tile = [&](const __half* A, const __half* B, int s, int b) {
        const uint32_t sa = sbase + (uint32_t)b * ST;
        const __half* As = A + s * BK;
        const __half* Bs = B + s * BK;
#pragma unroll
        for (int i = 0; i < 8; ++i) {
            cp_async16(sa + soff[i],        As + goff[i]);
            cp_async16(sa + A_ST + soff[i], Bs + goff[i]);
        }
        cp_commit();
    };

    int tile = blockIdx.x;                     // first tile: static
    {
        const __half* A0 = g_xq + (size_t)((tile >> 5) * BM) * I_;
        const __half* B0 = g_wq + (size_t)((tile & 31) * BN) * I_;
        issue_tile(A0, B0, 0, 0);
        issue_tile(A0, B0, 1, 1);
    }
    int buf = 0;

    uint32_t afr[4][4], bfr[4][4];

    while (tile < NTILES) {
        const int m0 = (tile >> 5) * BM;
        const int n0 = (tile & 31) * BN;
        const __half* Ag = g_xq + (size_t)m0 * I_;
        const __half* Bg = g_wq + (size_t)n0 * I_;

        if (tid == 0) s_nt = atomicAdd(&g_tile_ctr, 1);   // claim next tile

        int nt = NTILES;
        const __half* An = Ag;
        const __half* Bn = Bg;

        for (int s = 0; s < NUM_KT; ++s) {
            cp_wait<1>();                        // stage s resident (this thread)
            __syncthreads();                     // RAW stage-s data; WAR on the
                                                 // prefetch target buffer; also
                                                 // publishes s_nt at s==0

            if (s == 0) {
                nt = s_nt;
                if (nt < NTILES) {
                    An = g_xq + (size_t)((nt >> 5) * BM) * I_;
                    Bn = g_wq + (size_t)((nt & 31) * BN) * I_;
                }
            }

            const uint32_t bA = sbase + (uint32_t)buf * ST;
            const uint32_t bB = bA + A_ST;

#pragma unroll
            for (int mi = 0; mi < 4; ++mi)
                ldmatrix_x4(afr[mi],
                            bA + arow[mi] * 128 + ((acbit ^ (arow[mi] & 7)) << 4));
#pragma unroll
            for (int np = 0; np < 4; ++np)
                ldmatrix_x4(bfr[np],
                            bB + brow[np] * 128 + ((bcbit ^ (brow[np] & 7)) << 4));

            const int pbuf = buf ? buf - 1 : 2;  // (buf+2)%3
            const int ps = s + 2;
            if (ps < NUM_KT)       issue_tile(Ag, Bg, ps, pbuf);
            else if (nt < NTILES)  issue_tile(An, Bn, ps - NUM_KT, pbuf);
            else                   cp_commit();  // uniform group accounting

#pragma unroll
            for (int ks = 0; ks < 4; ++ks) {     // 4 x K=16 per stage
                const uint32_t ach = (uint32_t)((ks + 1) * 2) + acbit;
                const uint32_t bch = (uint32_t)((ks + 1) * 2) + bcbit;
#pragma unroll
                for (int mi = 0; mi < 4; ++mi) {
#pragma unroll
                    for (int ni = 0; ni < 8; ++ni)
                        mma16816(acc[mi][ni], afr[mi],
                                 bfr[ni >> 1][(ni & 1) * 2],
                                 bfr[ni >> 1][(ni & 1) * 2 + 1]);
                    if (ks < 3)                  // reload afr[mi] in place
                        ldmatrix_x4(afr[mi],
                                    bA + arow[mi] * 128 + ((ach ^ (arow[mi] & 7)) << 4));
                }
                if (ks < 3) {
#pragma unroll
                    for (int np = 0; np < 4; ++np)
                        ldmatrix_x4(bfr[np],
                                    bB + brow[np] * 128 + ((bch ^ (brow[np] & 7)) << 4));
                }
            }
            buf = (buf == 2) ? 0 : buf + 1;
        }

        // Epilogue (overlaps the next tile's in-flight loads)
#pragma unroll
        for (int mi = 0; mi < 4; ++mi) {
            const int grow = m0 + wm * 64 + mi * 16 + (lane >> 2);
            const float s0 = g_sx[grow];
            const float s1 = g_sx[grow + 8];
#pragma unroll
            for (int ni = 0; ni < 8; ++ni) {
                const int gcol = n0 + wn * 64 + ni * 8 + (lane & 3) * 2;
                float2 v0, v1;
                v0.x = acc[mi][ni][0] * s0; v0.y = acc[mi][ni][1] * s0;
                v1.x = acc[mi][ni][2] * s1; v1.y = acc[mi][ni][3] * s1;
                *reinterpret_cast<float2*>(C + (size_t)grow * O_ + gcol) = v0;
                *reinterpret_cast<float2*>(C + (size_t)(grow + 8) * O_ + gcol) = v1;
            }
        }

        tile = nt;
        if (tile < NTILES) {
#pragma unroll
            for (int a = 0; a < 4; ++a)
#pragma unroll
                for (int b = 0; b < 8; ++b)
#pragma unroll
                    for (int c = 0; c < 4; ++c) acc[a][b][c] = 0.0f;
        }
    }
}

// ---------------------------------------------------------------------------
// Launch
// ---------------------------------------------------------------------------
extern "C" void kernel_launch(void* const* d_in, const int* in_sizes, int n_in,
                              void* d_out, int out_size) {
    const float* x = (const float*)d_in[0];
    const int* w = (const int*)d_in[1];
    const float* scales = (const float*)d_in[2];
    const float* zeros = (const float*)d_in[3];
    float* out = (float*)d_out;

    static int nCTA = 0;
    if (nCTA == 0) {
        cudaFuncSetAttribute(gemm_kernel,
                             cudaFuncAttributeMaxDynamicSharedMemorySize,
                             GEMM_SMEM);
        int sms = 0;
        cudaDeviceGetAttribute(&sms, cudaDevAttrMultiProcessorCount, 0);
        nCTA = 2 * (sms > 0 ? sms : 148);
        if (nCTA > NTILES) nCTA = NTILES;
    }

    prep_kernel<<<T_ + (O_ * (I_ / 8)) / 256, 256>>>(x, w, scales, zeros, nCTA);
    gemm_kernel<<<nCTA, 128, GEMM_SMEM>>>(out);
}